// round 2
// baseline (speedup 1.0000x reference)
#include <cuda_runtime.h>

// out[b] = sum_j exp(-K2_j) * K2_j / sum_j exp(-K2_j),
// where K2_j = (x_j - mean(x))^2 over the all_atom_features of batch b.
// (softmax over j of -(Q2_i + K2_j) cancels the Q2_i term exactly, so the
//  cdr3 input does not affect the output.)

#define M 8192
#define NTHREADS 1024

__device__ __forceinline__ float block_reduce_sum(float v, float* red) {
    #pragma unroll
    for (int o = 16; o > 0; o >>= 1) v += __shfl_down_sync(0xffffffffu, v, o);
    int lane = threadIdx.x & 31;
    int wid  = threadIdx.x >> 5;
    if (lane == 0) red[wid] = v;
    __syncthreads();
    if (wid == 0) {
        v = (lane < (NTHREADS / 32)) ? red[lane] : 0.0f;
        #pragma unroll
        for (int o = 16; o > 0; o >>= 1) v += __shfl_down_sync(0xffffffffu, v, o);
        if (lane == 0) red[0] = v;
    }
    __syncthreads();
    float r = red[0];
    __syncthreads();   // protect red[] before next reuse
    return r;
}

__device__ __forceinline__ float block_reduce_min(float v, float* red) {
    #pragma unroll
    for (int o = 16; o > 0; o >>= 1) v = fminf(v, __shfl_down_sync(0xffffffffu, v, o));
    int lane = threadIdx.x & 31;
    int wid  = threadIdx.x >> 5;
    if (lane == 0) red[wid] = v;
    __syncthreads();
    if (wid == 0) {
        v = (lane < (NTHREADS / 32)) ? red[lane] : 3.402823466e+38f;
        #pragma unroll
        for (int o = 16; o > 0; o >>= 1) v = fminf(v, __shfl_down_sync(0xffffffffu, v, o));
        if (lane == 0) red[0] = v;
    }
    __syncthreads();
    float r = red[0];
    __syncthreads();
    return r;
}

__global__ __launch_bounds__(NTHREADS)
void invariant_cross_attention_kernel(const float* __restrict__ atom,
                                      float* __restrict__ out) {
    __shared__ float sdata[M];
    __shared__ float red[32];

    const int b   = blockIdx.x;
    const int tid = threadIdx.x;
    const float* __restrict__ x = atom + (size_t)b * M;

    // Pass 1: load into shared + sum (vectorized: 8 elems/thread = 2x float4)
    float sum = 0.0f;
    const float4* x4 = reinterpret_cast<const float4*>(x);
    float4* s4 = reinterpret_cast<float4*>(sdata);
    #pragma unroll
    for (int k = 0; k < (M / 4) / NTHREADS; k++) {
        int i = tid + k * NTHREADS;
        float4 v = x4[i];
        s4[i] = v;
        sum += v.x + v.y + v.z + v.w;
    }
    __syncthreads();
    float total = block_reduce_sum(sum, red);
    float mean = total * (1.0f / (float)M);

    // Pass 2: K2 = (x - mean)^2 in place; track min(K2) (= -max(-K2)) for shift
    float mn = 3.402823466e+38f;
    #pragma unroll
    for (int k = 0; k < M / NTHREADS; k++) {
        int i = tid + k * NTHREADS;
        float d = sdata[i] - mean;
        float k2 = d * d;
        sdata[i] = k2;
        mn = fminf(mn, k2);
    }
    __syncthreads();
    float m = block_reduce_min(mn, red);

    // Pass 3: s = sum exp(m - k2), num = sum exp(m - k2) * k2
    float s = 0.0f, num = 0.0f;
    #pragma unroll
    for (int k = 0; k < M / NTHREADS; k++) {
        int i = tid + k * NTHREADS;
        float k2 = sdata[i];
        float e = __expf(m - k2);
        s   += e;
        num += e * k2;
    }
    float s_tot   = block_reduce_sum(s, red);
    float num_tot = block_reduce_sum(num, red);

    if (tid == 0) {
        out[b] = num_tot / s_tot;
    }
}

extern "C" void kernel_launch(void* const* d_in, const int* in_sizes, int n_in,
                              void* d_out, int out_size) {
    // d_in[0] = cdr3_features [4, 2048, 1]  (mathematically irrelevant; unused)
    // d_in[1] = all_atom_features [4, 8192, 1]
    const float* atom = (const float*)d_in[1];
    float* out = (float*)d_out;
    const int B = in_sizes[1] / M;   // 4
    invariant_cross_attention_kernel<<<B, NTHREADS>>>(atom, out);
}